// round 1
// baseline (speedup 1.0000x reference)
#include <cuda_runtime.h>
#include <math_constants.h>

// FCOS decode:
//   inputs  : bbox [16,128,128,4] f32, center [16,128,128,1] f32, cls [16,128,128,80] f32
//   outputs : xywh [16,16384,4] f32 ++ cls_idx [16,16384] (as f32) ++ conf [16,16384] f32
// Grid geometry: nH=nW=128, STRIDE=8, center offset = 4.

#define N_LOC   (16 * 128 * 128)   // 262144
#define N_CLS   80
#define XYWH_ELEMS (N_LOC * 4)     // 1048576

__global__ __launch_bounds__(256)
void fcos_decode_kernel(const float* __restrict__ bbox,
                        const float* __restrict__ center,
                        const float* __restrict__ cls,
                        float* __restrict__ out)
{
    int loc = blockIdx.x * blockDim.x + threadIdx.x;
    if (loc >= N_LOC) return;

    // ---- class max / argmax (sigmoid is monotonic -> reduce on raw logits) ----
    const float4* c4 = reinterpret_cast<const float4*>(cls + (size_t)loc * N_CLS);
    float best = -CUDART_INF_F;
    int   bidx = 0;
#pragma unroll
    for (int j = 0; j < N_CLS / 4; ++j) {
        float4 v = c4[j];
        if (v.x > best) { best = v.x; bidx = 4 * j + 0; }
        if (v.y > best) { best = v.y; bidx = 4 * j + 1; }
        if (v.z > best) { best = v.z; bidx = 4 * j + 2; }
        if (v.w > best) { best = v.w; bidx = 4 * j + 3; }
    }

    // ---- bbox decode: ltrb = exp(raw)*8, then ltrb -> xywh on stride-8 grid ----
    float4 bb = reinterpret_cast<const float4*>(bbox)[loc];
    float l = __expf(bb.x) * 8.0f;
    float t = __expf(bb.y) * 8.0f;
    float r = __expf(bb.z) * 8.0f;
    float b = __expf(bb.w) * 8.0f;

    int h = (loc >> 7) & 127;
    int w =  loc       & 127;
    float cy = (float)h * 8.0f + 4.0f;
    float cx = (float)w * 8.0f + 4.0f;

    float4 xywh;
    xywh.x = cx - (l - r) * 0.5f;
    xywh.y = cy - (t - b) * 0.5f;
    xywh.z = l + r;
    xywh.w = t + b;

    // ---- confidence: sqrt(sigmoid(center) * sigmoid(max_logit)) ----
    float ctr = center[loc];
    float s_ctr = 1.0f / (1.0f + __expf(-ctr));
    float s_cls = 1.0f / (1.0f + __expf(-best));
    float conf  = sqrtf(s_ctr * s_cls);

    // ---- writes ----
    reinterpret_cast<float4*>(out)[loc]       = xywh;               // [16,16384,4]
    out[XYWH_ELEMS + loc]                     = (float)bidx;        // cls_idx
    out[XYWH_ELEMS + N_LOC + loc]             = conf;               // conf
}

extern "C" void kernel_launch(void* const* d_in, const int* in_sizes, int n_in,
                              void* d_out, int out_size)
{
    const float* bbox   = (const float*)d_in[0];
    const float* center = (const float*)d_in[1];
    const float* cls    = (const float*)d_in[2];
    float* out = (float*)d_out;

    const int threads = 256;
    const int blocks  = (N_LOC + threads - 1) / threads;  // 1024
    fcos_decode_kernel<<<blocks, threads>>>(bbox, center, cls, out);
}

// round 2
// speedup vs baseline: 1.1836x; 1.1836x over previous
#include <cuda_runtime.h>
#include <math_constants.h>

// FCOS decode, smem-staged class reduction for coalesced HBM access.
//   inputs  : bbox [16,128,128,4] f32, center [16,128,128,1] f32, cls [16,128,128,80] f32
//   outputs : xywh [16,16384,4] f32 ++ cls_idx [16,16384] (as f32) ++ conf [16,16384] f32

#define N_LOC      (16 * 128 * 128)   // 262144
#define N_CLS      80
#define XYWH_ELEMS (N_LOC * 4)

#define THREADS        256
#define LOCS_PER_BLOCK 256
#define TILE           64                       // locations per chunk
#define CHUNKS         (LOCS_PER_BLOCK / TILE)  // 4
#define F4_PER_ROW     (N_CLS / 4)              // 20
#define F4_PER_CHUNK   (TILE * F4_PER_ROW)      // 1280
#define F4_PER_THREAD  (F4_PER_CHUNK / THREADS) // 5

__global__ __launch_bounds__(THREADS)
void fcos_decode_kernel(const float4* __restrict__ cls4,
                        const float4* __restrict__ bbox4,
                        const float*  __restrict__ center,
                        float* __restrict__ out)
{
    __shared__ float4 sm[2][F4_PER_CHUNK];   // 2 x 20KB double buffer

    const int t    = threadIdx.x;
    const int base = blockIdx.x * LOCS_PER_BLOCK;
    const int row  = t >> 2;   // 0..63  (location within chunk)
    const int part = t & 3;    // 0..3   (20-class segment)

    float4 stage[F4_PER_THREAD];

    // ---- prologue: load chunk 0 (coalesced) ----
    {
        const float4* src = cls4 + (size_t)base * F4_PER_ROW;
        #pragma unroll
        for (int i = 0; i < F4_PER_THREAD; ++i)
            stage[i] = src[t + i * THREADS];
        #pragma unroll
        for (int i = 0; i < F4_PER_THREAD; ++i)
            sm[0][t + i * THREADS] = stage[i];
    }
    __syncthreads();

    #pragma unroll
    for (int c = 0; c < CHUNKS; ++c) {
        // ---- prefetch next chunk into registers (LDGs overlap the reduce) ----
        if (c + 1 < CHUNKS) {
            const float4* src = cls4 + (size_t)(base + (c + 1) * TILE) * F4_PER_ROW;
            #pragma unroll
            for (int i = 0; i < F4_PER_THREAD; ++i)
                stage[i] = src[t + i * THREADS];
        }

        // ---- per-thread partial max/argmax over 20 classes (sigmoid monotonic) ----
        const float4* my = &sm[c & 1][row * F4_PER_ROW + part * 5];
        float best = -CUDART_INF_F;
        int   bidx = 0;
        #pragma unroll
        for (int k = 0; k < 5; ++k) {
            float4 v = my[k];
            int b0 = part * 20 + k * 4;
            if (v.x > best) { best = v.x; bidx = b0 + 0; }
            if (v.y > best) { best = v.y; bidx = b0 + 1; }
            if (v.z > best) { best = v.z; bidx = b0 + 2; }
            if (v.w > best) { best = v.w; bidx = b0 + 3; }
        }

        // ---- combine the 4 segment-partials (tie -> lowest class index) ----
        #pragma unroll
        for (int off = 1; off <= 2; off <<= 1) {
            float ob = __shfl_xor_sync(0xffffffffu, best, off);
            int   oi = __shfl_xor_sync(0xffffffffu, bidx, off);
            if (ob > best || (ob == best && oi < bidx)) { best = ob; bidx = oi; }
        }

        // ---- owner lane: bbox decode + confidence + writes ----
        if (part == 0) {
            int loc = base + c * TILE + row;

            float4 bb = bbox4[loc];
            float l  = __expf(bb.x) * 8.0f;
            float tt = __expf(bb.y) * 8.0f;
            float r  = __expf(bb.z) * 8.0f;
            float bo = __expf(bb.w) * 8.0f;

            int h = (loc >> 7) & 127;
            int w =  loc       & 127;

            float4 xywh;
            xywh.x = ((float)w * 8.0f + 4.0f) - (l  - r ) * 0.5f;
            xywh.y = ((float)h * 8.0f + 4.0f) - (tt - bo) * 0.5f;
            xywh.z = l  + r;
            xywh.w = tt + bo;

            float s_ctr = 1.0f / (1.0f + __expf(-center[loc]));
            float s_cls = 1.0f / (1.0f + __expf(-best));

            reinterpret_cast<float4*>(out)[loc] = xywh;
            out[XYWH_ELEMS + loc]               = (float)bidx;
            out[XYWH_ELEMS + N_LOC + loc]       = sqrtf(s_ctr * s_cls);
        }

        // ---- commit prefetched chunk to the other buffer ----
        if (c + 1 < CHUNKS) {
            #pragma unroll
            for (int i = 0; i < F4_PER_THREAD; ++i)
                sm[(c + 1) & 1][t + i * THREADS] = stage[i];
            __syncthreads();
        }
    }
}

extern "C" void kernel_launch(void* const* d_in, const int* in_sizes, int n_in,
                              void* d_out, int out_size)
{
    const float* bbox   = (const float*)d_in[0];
    const float* center = (const float*)d_in[1];
    const float* cls    = (const float*)d_in[2];
    float* out = (float*)d_out;

    const int blocks = N_LOC / LOCS_PER_BLOCK;  // 1024
    fcos_decode_kernel<<<blocks, THREADS>>>(
        reinterpret_cast<const float4*>(cls),
        reinterpret_cast<const float4*>(bbox),
        center, out);
}

// round 3
// speedup vs baseline: 1.3454x; 1.1366x over previous
#include <cuda_runtime.h>
#include <cuda_pipeline.h>
#include <math_constants.h>

// FCOS decode, cp.async double-buffered smem staging.
//   inputs  : bbox [16,128,128,4] f32, center [16,128,128,1] f32, cls [16,128,128,80] f32
//   outputs : xywh [16,16384,4] f32 ++ cls_idx [16,16384] (as f32) ++ conf [16,16384] f32

#define N_LOC      (16 * 128 * 128)   // 262144
#define N_CLS      80
#define XYWH_ELEMS (N_LOC * 4)

#define THREADS        256
#define LOCS_PER_BLOCK 256
#define TILE           64                       // locations per chunk
#define CHUNKS         (LOCS_PER_BLOCK / TILE)  // 4
#define F4_PER_ROW     (N_CLS / 4)              // 20
#define F4_PER_CHUNK   (TILE * F4_PER_ROW)      // 1280
#define F4_PER_THREAD  (F4_PER_CHUNK / THREADS) // 5

__global__ __launch_bounds__(THREADS)
void fcos_decode_kernel(const float4* __restrict__ cls4,
                        const float4* __restrict__ bbox4,
                        const float*  __restrict__ center,
                        float* __restrict__ out)
{
    __shared__ float4 sm[2][F4_PER_CHUNK];   // 2 x 20KB double buffer

    const int t    = threadIdx.x;
    const int base = blockIdx.x * LOCS_PER_BLOCK;
    const int row  = t >> 2;   // 0..63  (location within chunk)
    const int part = t & 3;    // 0..3   (20-class segment)

    // ---- prologue: async-load chunk 0 ----
    {
        const float4* src = cls4 + (size_t)base * F4_PER_ROW;
        #pragma unroll
        for (int i = 0; i < F4_PER_THREAD; ++i)
            __pipeline_memcpy_async(&sm[0][t + i * THREADS],
                                    &src[t + i * THREADS], 16);
        __pipeline_commit();
    }

    #pragma unroll
    for (int c = 0; c < CHUNKS; ++c) {
        // ---- issue async load of next chunk into the other buffer ----
        if (c + 1 < CHUNKS) {
            const float4* src = cls4 + (size_t)(base + (c + 1) * TILE) * F4_PER_ROW;
            #pragma unroll
            for (int i = 0; i < F4_PER_THREAD; ++i)
                __pipeline_memcpy_async(&sm[(c + 1) & 1][t + i * THREADS],
                                        &src[t + i * THREADS], 16);
            __pipeline_commit();
            __pipeline_wait_prior(1);   // chunk c resident, c+1 in flight
        } else {
            __pipeline_wait_prior(0);   // last chunk resident
        }
        __syncthreads();

        // ---- per-thread partial max/argmax over 20 classes (sigmoid monotonic) ----
        const float4* my = &sm[c & 1][row * F4_PER_ROW + part * 5];
        float best = -CUDART_INF_F;
        int   bidx = 0;
        #pragma unroll
        for (int k = 0; k < 5; ++k) {
            float4 v = my[k];
            int b0 = part * 20 + k * 4;
            if (v.x > best) { best = v.x; bidx = b0 + 0; }
            if (v.y > best) { best = v.y; bidx = b0 + 1; }
            if (v.z > best) { best = v.z; bidx = b0 + 2; }
            if (v.w > best) { best = v.w; bidx = b0 + 3; }
        }

        // ---- combine the 4 segment-partials (tie -> lowest class index) ----
        #pragma unroll
        for (int off = 1; off <= 2; off <<= 1) {
            float ob = __shfl_xor_sync(0xffffffffu, best, off);
            int   oi = __shfl_xor_sync(0xffffffffu, bidx, off);
            if (ob > best || (ob == best && oi < bidx)) { best = ob; bidx = oi; }
        }

        // ---- owner lane: bbox decode + confidence + writes ----
        if (part == 0) {
            int loc = base + c * TILE + row;

            float4 bb = bbox4[loc];
            float l  = __expf(bb.x) * 8.0f;
            float tt = __expf(bb.y) * 8.0f;
            float r  = __expf(bb.z) * 8.0f;
            float bo = __expf(bb.w) * 8.0f;

            int h = (loc >> 7) & 127;
            int w =  loc       & 127;

            float4 xywh;
            xywh.x = ((float)w * 8.0f + 4.0f) - (l  - r ) * 0.5f;
            xywh.y = ((float)h * 8.0f + 4.0f) - (tt - bo) * 0.5f;
            xywh.z = l  + r;
            xywh.w = tt + bo;

            float s_ctr = 1.0f / (1.0f + __expf(-center[loc]));
            float s_cls = 1.0f / (1.0f + __expf(-best));

            reinterpret_cast<float4*>(out)[loc] = xywh;
            out[XYWH_ELEMS + loc]               = (float)bidx;
            out[XYWH_ELEMS + N_LOC + loc]       = sqrtf(s_ctr * s_cls);
        }

        // ---- all reads of buffer (c & 1) done before chunk c+2 overwrites it ----
        if (c + 2 < CHUNKS + 1) __syncthreads();
    }
}

extern "C" void kernel_launch(void* const* d_in, const int* in_sizes, int n_in,
                              void* d_out, int out_size)
{
    const float* bbox   = (const float*)d_in[0];
    const float* center = (const float*)d_in[1];
    const float* cls    = (const float*)d_in[2];
    float* out = (float*)d_out;

    const int blocks = N_LOC / LOCS_PER_BLOCK;  // 1024
    fcos_decode_kernel<<<blocks, THREADS>>>(
        reinterpret_cast<const float4*>(cls),
        reinterpret_cast<const float4*>(bbox),
        center, out);
}